// round 12
// baseline (speedup 1.0000x reference)
#include <cuda_runtime.h>
#include <cuda_fp16.h>
#include <stdint.h>
#include <float.h>
#include <math.h>

// Problem constants
#define HIDDEN 1024
#define HEADS  16
#define HDIM   64
#define B      2
#define T      2048
#define QKV3   (3 * HIDDEN)
#define BT     (B * T)        // 4096

// ---------------- scratch (static device globals; no allocation) -------------
__device__ __half g_qh[(size_t)B * HEADS * T * HDIM];      // [b,h,t,d] fp16 (RoPE'd)
__device__ __half g_kh[(size_t)B * HEADS * T * HDIM];
__device__ __half g_vh[(size_t)B * HEADS * T * HDIM];
__device__ __half g_ctx[(size_t)BT * HIDDEN];              // [b,t,hidden] fp16
__device__ __half g_xh[(size_t)BT * HIDDEN];               // fp16 x
__device__ __half g_wqkvh[(size_t)QKV3 * HIDDEN];          // fp16 qkv_w
__device__ __half g_wouth[(size_t)HIDDEN * HIDDEN];        // fp16 out_w
__device__ float2 g_cs[(size_t)T * 32];                    // cos/sin table

__device__ __forceinline__ uint32_t smem_u32(const void* p) {
    uint32_t a;
    asm("{ .reg .u64 t; cvta.to.shared.u64 t, %1; cvt.u32.u64 %0, t; }"
        : "=r"(a) : "l"(p));
    return a;
}

#define CP_ASYNC16(dst, src) \
    asm volatile("cp.async.ca.shared.global [%0], [%1], 16;" :: "r"(dst), "l"(src))
#define CP_COMMIT() asm volatile("cp.async.commit_group;" ::: "memory")
#define CP_WAIT0() asm volatile("cp.async.wait_group 0;" ::: "memory")
#define CP_WAIT1() asm volatile("cp.async.wait_group 1;" ::: "memory")

// f16 mma: D(16x8,f32) += A(16x16,f16) * B(16x8,f16)
__device__ __forceinline__ void mma_f16(float* c, const uint32_t* a, uint32_t b0, uint32_t b1) {
    asm volatile(
        "mma.sync.aligned.m16n8k16.row.col.f32.f16.f16.f32 "
        "{%0,%1,%2,%3}, {%4,%5,%6,%7}, {%8,%9}, {%0,%1,%2,%3};"
        : "+f"(c[0]), "+f"(c[1]), "+f"(c[2]), "+f"(c[3])
        : "r"(a[0]), "r"(a[1]), "r"(a[2]), "r"(a[3]), "r"(b0), "r"(b1));
}

#define LDSM_X4(r0, r1, r2, r3, addr) \
    asm volatile("ldmatrix.sync.aligned.m8n8.x4.shared.b16 {%0,%1,%2,%3}, [%4];" \
                 : "=r"(r0), "=r"(r1), "=r"(r2), "=r"(r3) : "r"(addr))
#define LDSM_X4_T(r0, r1, r2, r3, addr) \
    asm volatile("ldmatrix.sync.aligned.m8n8.x4.trans.shared.b16 {%0,%1,%2,%3}, [%4];" \
                 : "=r"(r0), "=r"(r1), "=r"(r2), "=r"(r3) : "r"(addr))

// ---------------- fp32 -> fp16 convert ---------------------------------------
__global__ void to_half(const float* __restrict__ src, __half* __restrict__ dst, int n8)
{
    int i = blockIdx.x * blockDim.x + threadIdx.x;
    if (i >= n8) return;
    float4 a = ((const float4*)src)[i * 2];
    float4 b = ((const float4*)src)[i * 2 + 1];
    __half2 h0 = __floats2half2_rn(a.x, a.y);
    __half2 h1 = __floats2half2_rn(a.z, a.w);
    __half2 h2 = __floats2half2_rn(b.x, b.y);
    __half2 h3 = __floats2half2_rn(b.z, b.w);
    uint4 u;
    u.x = *(const uint32_t*)&h0; u.y = *(const uint32_t*)&h1;
    u.z = *(const uint32_t*)&h2; u.w = *(const uint32_t*)&h3;
    ((uint4*)dst)[i] = u;
}

// ---------------- cos/sin table ----------------------------------------------
__global__ void build_cs(void)
{
    int idx = blockIdx.x * blockDim.x + threadIdx.x;
    if (idx >= T * 32) return;
    int i = idx & 31;
    int t = idx >> 5;
    float inv = 1.0f / powf(10000.0f, (float)(2 * i) / 64.0f);
    float ang = (float)t * inv;
    g_cs[idx] = make_float2(cosf(ang), sinf(ang));
}

// ========= fp16 mma GEMM: C[M,N] = A[M,K] @ W[N,K]^T + bias ==================
// CTA 128x256, 8 warps (warp 64x64), BK=64 halves, 3-stage cp.async,
// ldmatrix fragment loads. MODE 0: bias + fp32 C. MODE 1: qkv+RoPE epilogue.
#define BKC 64
#define HSTR 72                         // halves per row
#define STG_A_H (128 * HSTR)
#define STG_H ((128 + 256) * HSTR)      // halves per stage
#define NSTG 3
#define TSM_BYTES (NSTG * STG_H * 2)    // 165888

template <int MODE>
__global__ __launch_bounds__(256, 1) void mma_gemm(
    const __half* __restrict__ A, const __half* __restrict__ W,
    const float* __restrict__ bias, float* __restrict__ C,
    int Nt, int K)
{
    extern __shared__ __half smh[];
    const int tid = threadIdx.x;
    const int wid = tid >> 5;
    const int lane = tid & 31;
    const int g = lane >> 2;
    const int t = lane & 3;
    const int bm = blockIdx.y * 128;
    const int bn = blockIdx.x * 256;
    const int warpM = wid & 1;
    const int warpN = wid >> 1;

    const int lrow = tid >> 1;
    const int lh = tid & 1;
    const uint32_t sb = smem_u32(smh);
    const __half* gA = A + (size_t)(bm + lrow) * K + lh * 32;
    const __half* gW0 = W + (size_t)(bn + lrow) * K + lh * 32;
    const __half* gW1 = W + (size_t)(bn + 128 + lrow) * K + lh * 32;
    const uint32_t soff = (lrow * HSTR + lh * 32) * 2;

    // ldmatrix lane offsets (bytes)
    const uint32_t aLaneOff = (uint32_t)((lane & 15) * HSTR + (lane >> 4) * 8) * 2;
    const uint32_t bLaneOff =
        (uint32_t)(((((lane >> 4) & 1) * 8 + (lane & 7)) * HSTR) + ((lane >> 3) & 1) * 8) * 2;

    float acc[4][8][4];
#pragma unroll
    for (int mi = 0; mi < 4; mi++)
#pragma unroll
        for (int ni = 0; ni < 8; ni++)
#pragma unroll
            for (int e = 0; e < 4; e++) acc[mi][ni][e] = 0.f;

    const int NC = K / BKC;   // 16

#define ISSUE_CHUNK(c)                                                          \
    do {                                                                        \
        const uint32_t base = sb + ((c) % NSTG) * (STG_H * 2);                  \
        const int k0 = (c) * BKC;                                               \
        _Pragma("unroll")                                                       \
        for (int q = 0; q < 4; q++) {                                           \
            CP_ASYNC16(base + soff + q * 16, gA + k0 + q * 8);                  \
            CP_ASYNC16(base + STG_A_H * 2 + soff + q * 16, gW0 + k0 + q * 8);   \
            CP_ASYNC16(base + (STG_A_H + 128 * HSTR) * 2 + soff + q * 16, gW1 + k0 + q * 8); \
        }                                                                       \
        CP_COMMIT();                                                            \
    } while (0)

    ISSUE_CHUNK(0);
    ISSUE_CHUNK(1);

    for (int c = 0; c < NC; c++) {
        if (c + 1 < NC) CP_WAIT1(); else CP_WAIT0();
        __syncthreads();
        if (c + 2 < NC) ISSUE_CHUNK(c + 2);

        const uint32_t stg = sb + (c % NSTG) * (STG_H * 2);
        const uint32_t aWarp = stg + (uint32_t)(warpM * 64 * HSTR) * 2 + aLaneOff;
        const uint32_t wWarp = stg + STG_A_H * 2 + (uint32_t)(warpN * 64 * HSTR) * 2 + bLaneOff;

        uint32_t af[2][4][4], bq[2][4][4];
#define LOAD_FRAGS(buf, kh)                                                     \
    do {                                                                        \
        _Pragma("unroll")                                                       \
        for (int mi = 0; mi < 4; mi++)                                          \
            LDSM_X4(af[buf][mi][0], af[buf][mi][1], af[buf][mi][2], af[buf][mi][3], \
                    aWarp + (uint32_t)(mi * 16 * HSTR + (kh)) * 2);             \
        _Pragma("unroll")                                                       \
        for (int fp = 0; fp < 4; fp++)                                          \
            LDSM_X4(bq[buf][fp][0], bq[buf][fp][1], bq[buf][fp][2], bq[buf][fp][3], \
                    wWarp + (uint32_t)(fp * 16 * HSTR + (kh)) * 2);             \
    } while (0)

        LOAD_FRAGS(0, 0);
#pragma unroll
        for (int ks = 0; ks < 4; ks++) {
            const int cur = ks & 1;
            if (ks < 3) LOAD_FRAGS(cur ^ 1, (ks + 1) * 16);
#pragma unroll
            for (int mi = 0; mi < 4; mi++)
#pragma unroll
                for (int fp = 0; fp < 4; fp++) {
                    mma_f16(acc[mi][fp * 2], af[cur][mi], bq[cur][fp][0], bq[cur][fp][1]);
                    mma_f16(acc[mi][fp * 2 + 1], af[cur][mi], bq[cur][fp][2], bq[cur][fp][3]);
                }
        }
#undef LOAD_FRAGS
    }

    if (MODE == 0) {
#pragma unroll
        for (int mi = 0; mi < 4; mi++) {
            const int row0 = bm + warpM * 64 + mi * 16 + g;
#pragma unroll
            for (int ni = 0; ni < 8; ni++) {
                const int col = bn + warpN * 64 + ni * 8 + 2 * t;
                const float bx = bias[col], by = bias[col + 1];
                float2 r0, r1;
                r0.x = acc[mi][ni][0] + bx; r0.y = acc[mi][ni][1] + by;
                r1.x = acc[mi][ni][2] + bx; r1.y = acc[mi][ni][3] + by;
                *(float2*)(C + (size_t)row0 * Nt + col) = r0;
                *(float2*)(C + (size_t)(row0 + 8) * Nt + col) = r1;
            }
        }
    } else {
        // qkv epilogue: warp slab = one head of q/k/v. bias + RoPE + fp16 scatter.
        const int col0 = bn + warpN * 64;
        const int region = col0 >> 10;               // 0=q 1=k 2=v
        const int h = (col0 & 1023) >> 6;
        __half* dst = (region == 0) ? g_qh : (region == 1) ? g_kh : g_vh;
#pragma unroll
        for (int mi = 0; mi < 4; mi++) {
            const int rowg = bm + warpM * 64 + mi * 16 + g;
#pragma unroll
            for (int rs = 0; rs < 2; rs++) {
                const int row = rowg + rs * 8;
                const int tt = row & (T - 1);
                const int bb = row >> 11;
                __half* op = dst + ((size_t)(bb * HEADS + h) * T + tt) * HDIM;
                const float2* cs = g_cs + tt * 32;
#pragma unroll
                for (int ni = 0; ni < 4; ni++) {
#pragma unroll
                    for (int e = 0; e < 2; e++) {
                        const int d = ni * 8 + 2 * t + e;
                        float v1 = acc[mi][ni][rs * 2 + e] + bias[col0 + d];
                        float v2 = acc[mi][ni + 4][rs * 2 + e] + bias[col0 + d + 32];
                        if (region < 2) {
                            float2 c = cs[d];
                            op[d]      = __float2half_rn(v1 * c.x - v2 * c.y);
                            op[d + 32] = __float2half_rn(v1 * c.y + v2 * c.x);
                        } else {
                            op[d]      = __float2half_rn(v1);
                            op[d + 32] = __float2half_rn(v2);
                        }
                    }
                }
            }
        }
    }
#undef ISSUE_CHUNK
}

// ================== fp16 tensor-core flash attention =========================
#define HSTRF 72
#define FK_H (64 * HSTRF)
#define FSTG_H (2 * FK_H)
#define FSM_BYTES (2 * FSTG_H * 2)

__global__ __launch_bounds__(128) void flash_mma(
    const int* __restrict__ ids, const long long* __restrict__ gidx, int n_g)
{
    extern __shared__ __half fsm[];
    __shared__ int s_anyg;

    const int tid = threadIdx.x;
    const int w = tid >> 5;
    const int lane = tid & 31;
    const int g = lane >> 2;
    const int t = lane & 3;
    const int qb = blockIdx.x;
    const int h = blockIdx.y;
    const int b = blockIdx.z;
    const int bh = b * HEADS + h;
    const int qrow0 = qb * 128;

    if (tid == 0) s_anyg = 0;
    __syncthreads();
    {
        int myid = ids[b * T + qrow0 + tid];
        bool myg = false;
        for (int i = 0; i < n_g; i++) myg |= (myid == (int)gidx[i]);
        if (myg) s_anyg = 1;
    }
    unsigned gmask;
    {
        int rid = ids[b * T + qrow0 + w * 32 + lane];
        bool rg = false;
        for (int i = 0; i < n_g; i++) rg |= (rid == (int)gidx[i]);
        gmask = __ballot_sync(0xffffffffu, rg);
    }
    __syncthreads();
    const int ktmax = s_anyg ? (T / 64 - 1) : (2 * qb + 1);

    uint32_t q[2][4][4];
    {
        const __half* Qb = g_qh + ((size_t)bh * T + qrow0 + w * 32) * HDIM;
        const __half2 qsc = __floats2half2_rn(0.125f, 0.125f);
#pragma unroll
        for (int rb = 0; rb < 2; rb++)
#pragma unroll
            for (int ks = 0; ks < 4; ks++) {
                const __half* b0 = Qb + (rb * 16 + g) * HDIM + ks * 16 + 2 * t;
                const __half* b1 = Qb + (rb * 16 + 8 + g) * HDIM + ks * 16 + 2 * t;
                __half2 a0 = __hmul2(*(const __half2*)b0, qsc);
                __half2 a1 = __hmul2(*(const __half2*)b1, qsc);
                __half2 a2 = __hmul2(*(const __half2*)(b0 + 8), qsc);
                __half2 a3 = __hmul2(*(const __half2*)(b1 + 8), qsc);
                q[rb][ks][0] = *(uint32_t*)&a0;
                q[rb][ks][1] = *(uint32_t*)&a1;
                q[rb][ks][2] = *(uint32_t*)&a2;
                q[rb][ks][3] = *(uint32_t*)&a3;
            }
    }

    float o[2][8][4];
#pragma unroll
    for (int rb = 0; rb < 2; rb++)
#pragma unroll
        for (int f = 0; f < 8; f++)
#pragma unroll
            for (int e = 0; e < 4; e++) o[rb][f][e] = 0.f;
    float m_[2][2], l_[2][2];
#pragma unroll
    for (int rb = 0; rb < 2; rb++)
#pragma unroll
        for (int hh = 0; hh < 2; hh++) { m_[rb][hh] = -1e30f; l_[rb][hh] = 0.f; }

    const __half* Kgb = g_kh + (size_t)bh * T * HDIM;
    const __half* Vgb = g_vh + (size_t)bh * T * HDIM;
    const uint32_t fsb = smem_u32(fsm);

    const int keyLK = ((lane >> 4) & 1) * 8 + (lane & 7);
    const int dLK = ((lane >> 3) & 1) * 8;
    const int keyLV = ((lane >> 3) & 1) * 8 + (lane & 7);
    const int dLV = (lane >> 4) * 8;
    const uint32_t kLaneOff = (uint32_t)(keyLK * HSTRF + dLK) * 2;
    const uint32_t vLaneOff = (uint32_t)(keyLV * HSTRF + dLV) * 2;

#define FISSUE(kt)                                                              \
    do {                                                                        \
        const uint32_t base = fsb + ((kt) & 1) * (FSTG_H * 2);                  \
        const __half* Ksrc = Kgb + (size_t)(kt) * 64 * HDIM;                    \
        const __half* Vsrc = Vgb + (size_t)(kt) * 64 * HDIM;                    \
        _Pragma("unroll")                                                       \
        for (int j = 0; j < 4; j++) {                                           \
            int idx = tid + j * 128;                                            \
            int r = idx >> 3;                                                   \
            int s8 = idx & 7;                                                   \
            CP_ASYNC16(base + (r * HSTRF + s8 * 8) * 2, Ksrc + r * HDIM + s8 * 8); \
            CP_ASYNC16(base + (FK_H + r * HSTRF + s8 * 8) * 2, Vsrc + r * HDIM + s8 * 8); \
        }                                                                       \
        CP_COMMIT();                                                            \
    } while (0)

    FISSUE(0);

    for (int kt = 0; kt <= ktmax; kt++) {
        __syncthreads();
        if (kt + 1 <= ktmax) { FISSUE(kt + 1); CP_WAIT1(); } else { CP_WAIT0(); }
        __syncthreads();
        const uint32_t ksm = fsb + (kt & 1) * (FSTG_H * 2);
        const uint32_t vsm = ksm + FK_H * 2;

        float s[2][8][4];
#pragma unroll
        for (int rb = 0; rb < 2; rb++)
#pragma unroll
            for (int f = 0; f < 8; f++)
#pragma unroll
                for (int e = 0; e < 4; e++) s[rb][f][e] = 0.f;
#pragma unroll
        for (int ks = 0; ks < 4; ks++) {
#pragma unroll
            for (int fp = 0; fp < 4; fp++) {
                uint32_t b0, b1, b2, b3;
                uint32_t addr = ksm + kLaneOff + (uint32_t)(fp * 16 * HSTRF + ks * 16) * 2;
                LDSM_X4(b0, b1, b2, b3, addr);
                mma_f16(s[0][fp * 2], q[0][ks], b0, b1);
                mma_f16(s[1][fp * 2], q[1][ks], b0, b1);
                mma_f16(s[0][fp * 2 + 1], q[0][ks], b2, b3);
                mma_f16(s[1][fp * 2 + 1], q[1][ks], b2, b3);
            }
        }

        uint32_t ap[2][4][4];
#pragma unroll
        for (int rb = 0; rb < 2; rb++) {
#pragma unroll
            for (int hh = 0; hh < 2; hh++) {
                const int rloc = rb * 16 + hh * 8 + g;
                const int grow = qrow0 + w * 32 + rloc;
                const bool rowg = (gmask >> rloc) & 1u;
                float pv[16];
                float mx = -1e30f;
                const bool fullok = (kt * 64 + 63 <= grow) || rowg;
#pragma unroll
                for (int f = 0; f < 8; f++) {
#pragma unroll
                    for (int e = 0; e < 2; e++) {
                        float sv = s[rb][f][hh * 2 + e];
                        if (!fullok) {
                            int col = kt * 64 + f * 8 + 2 * t + e;
                            if (col > grow) sv = -1e30f;
                        }
                        pv[f * 2 + e] = sv;
                        mx = fmaxf(mx, sv);
                    }
                }
                mx = fmaxf(mx, __shfl_xor_sync(0xffffffffu, mx, 1));
                mx = fmaxf(mx, __shfl_xor_sync(0xffffffffu, mx, 2));
                float mold = m_[rb][hh];
                float mnew = fmaxf(mold, mx);
                float corr = __expf(mold - mnew);
                float lsum = 0.f;
#pragma unroll
                for (int i = 0; i < 16; i++) {
                    float p = __expf(pv[i] - mnew);
                    pv[i] = p;
                    lsum += p;
                }
                lsum += __shfl_xor_sync(0xffffffffu, lsum, 1);
                lsum += __shfl_xor_sync(0xffffffffu, lsum, 2);
                m_[rb][hh] = mnew;
                l_[rb][hh] = l_[rb][hh] * corr + lsum;
#pragma unroll
                for (int f = 0; f < 8; f++) {
                    o[rb][f][hh * 2] *= corr;
                    o[rb][f][hh * 2 + 1] *= corr;
                }
#pragma unroll
                for (int ks = 0; ks < 4; ks++) {
                    __half2 lo = __floats2half2_rn(pv[4 * ks], pv[4 * ks + 1]);
                    __half2 hi = __floats2half2_rn(pv[4 * ks + 2], pv[4 * ks + 3]);
                    ap[rb][ks][hh] = *(uint32_t*)&lo;
                    ap[rb][ks][2 + hh] = *(uint32_t*)&hi;
                }
            }
        }

#pragma unroll
        for (int ks = 0; ks < 4; ks++) {
#pragma unroll
            for (int fp = 0; fp < 4; fp++) {
                uint32_t b0, b1, b2, b3;
                uint32_t addr = vsm + vLaneOff + (uint32_t)(ks * 16 * HSTRF + fp * 16) * 2;
                LDSM_X4_T(b0, b1, b2, b3, addr);
                mma_f16(o[0][fp * 2], ap[0][ks], b0, b1);
                mma_f16(o[1][fp * 2], ap[1][ks], b0, b1);
                mma_f16(o[0][fp * 2 + 1], ap[0][ks], b2, b3);
                mma_f16(o[1][fp * 2 + 1], ap[1][ks], b2, b3);
            }
        }
    }
#undef FISSUE

#pragma unroll
    for (int rb = 0; rb < 2; rb++) {
#pragma unroll
        for (int hh = 0; hh < 2; hh++) {
            float invl = 1.0f / l_[rb][hh];
            int trow = qrow0 + w * 32 + rb * 16 + hh * 8 + g;
            __half* op = g_ctx + ((size_t)b * T + trow) * HIDDEN + h * 64;
#pragma unroll
            for (int f = 0; f < 8; f++) {
                __half2 hr = __floats2half2_rn(o[rb][f][hh * 2] * invl,
                                               o[rb][f][hh * 2 + 1] * invl);
                *(__half2*)(op + f * 8 + 2 * t) = hr;
            }
        }
    }
}

// ---------------- host launch ------------------------------------------------
extern "C" void kernel_launch(void* const* d_in, const int* in_sizes, int n_in,
                              void* d_out, int out_size)
{
    const float* x      = (const float*)d_in[0];
    const int*   ids    = (const int*)d_in[1];
    const float* qkv_w  = (const float*)d_in[2];
    const float* qkv_b  = (const float*)d_in[3];
    const float* out_w  = (const float*)d_in[4];
    const float* out_b  = (const float*)d_in[5];
    const long long* gi = (const long long*)d_in[6];
    const int n_g = in_sizes[6];
    float* out = (float*)d_out;

    __half *p_xh, *p_wqkvh, *p_wouth, *p_ctx;
    cudaGetSymbolAddress((void**)&p_xh, g_xh);
    cudaGetSymbolAddress((void**)&p_wqkvh, g_wqkvh);
    cudaGetSymbolAddress((void**)&p_wouth, g_wouth);
    cudaGetSymbolAddress((void**)&p_ctx, g_ctx);

    cudaFuncSetAttribute(mma_gemm<0>,
                         cudaFuncAttributeMaxDynamicSharedMemorySize, TSM_BYTES);
    cudaFuncSetAttribute(mma_gemm<1>,
                         cudaFuncAttributeMaxDynamicSharedMemorySize, TSM_BYTES);
    cudaFuncSetAttribute(flash_mma,
                         cudaFuncAttributeMaxDynamicSharedMemorySize, FSM_BYTES);

    // 0) converts + cos/sin table
    to_half<<<(BT * HIDDEN / 8 + 255) / 256, 256>>>(x, p_xh, BT * HIDDEN / 8);
    to_half<<<(QKV3 * HIDDEN / 8 + 255) / 256, 256>>>(qkv_w, p_wqkvh, QKV3 * HIDDEN / 8);
    to_half<<<(HIDDEN * HIDDEN / 8 + 255) / 256, 256>>>(out_w, p_wouth, HIDDEN * HIDDEN / 8);
    build_cs<<<(T * 32 + 255) / 256, 256>>>();

    // 1) QKV projection + bias + RoPE + fp16 scatter to g_qh/g_kh/g_vh
    {
        dim3 grid(QKV3 / 256, BT / 128);
        mma_gemm<1><<<grid, 256, TSM_BYTES>>>(p_xh, p_wqkvh, qkv_b, nullptr, QKV3, HIDDEN);
    }
    // 2) Flash attention (fp16 tensor cores, register-resident P)
    {
        dim3 grid(T / 128, HEADS, B);
        flash_mma<<<grid, 128, FSM_BYTES>>>(ids, gi, n_g);
    }
    // 3) Output projection (fp16 operands, fp32 accum/output)
    {
        dim3 grid(HIDDEN / 256, BT / 128);
        mma_gemm<0><<<grid, 256, TSM_BYTES>>>(p_ctx, p_wouth, out_b, out, HIDDEN, HIDDEN);
    }
}

// round 16
// speedup vs baseline: 1.5112x; 1.5112x over previous
#include <cuda_runtime.h>
#include <cuda_fp16.h>
#include <stdint.h>
#include <float.h>
#include <math.h>

// Problem constants
#define HIDDEN 1024
#define HEADS  16
#define HDIM   64
#define B      2
#define T      2048
#define QKV3   (3 * HIDDEN)
#define BT     (B * T)        // 4096

// ---------------- scratch (static device globals; no allocation) -------------
__device__ __half g_qh[(size_t)B * HEADS * T * HDIM];      // [b,h,t,d] fp16 (RoPE'd)
__device__ __half g_kh[(size_t)B * HEADS * T * HDIM];
__device__ __half g_vh[(size_t)B * HEADS * T * HDIM];
__device__ __half g_ctx[(size_t)BT * HIDDEN];              // [b,t,hidden] fp16
__device__ __half g_xh[(size_t)BT * HIDDEN];               // fp16 x
__device__ __half g_wqkvh[(size_t)QKV3 * HIDDEN];          // fp16 qkv_w
__device__ __half g_wouth[(size_t)HIDDEN * HIDDEN];        // fp16 out_w
__device__ float2 g_cs[(size_t)T * 32];                    // cos/sin table

__device__ __forceinline__ uint32_t smem_u32(const void* p) {
    uint32_t a;
    asm("{ .reg .u64 t; cvta.to.shared.u64 t, %1; cvt.u32.u64 %0, t; }"
        : "=r"(a) : "l"(p));
    return a;
}

#define CP_ASYNC16(dst, src) \
    asm volatile("cp.async.ca.shared.global [%0], [%1], 16;" :: "r"(dst), "l"(src))
#define CP_COMMIT() asm volatile("cp.async.commit_group;" ::: "memory")
#define CP_WAIT0() asm volatile("cp.async.wait_group 0;" ::: "memory")
#define CP_WAIT1() asm volatile("cp.async.wait_group 1;" ::: "memory")

// f16 mma: D(16x8,f32) += A(16x16,f16) * B(16x8,f16)
__device__ __forceinline__ void mma_f16(float* c, const uint32_t* a, uint32_t b0, uint32_t b1) {
    asm volatile(
        "mma.sync.aligned.m16n8k16.row.col.f32.f16.f16.f32 "
        "{%0,%1,%2,%3}, {%4,%5,%6,%7}, {%8,%9}, {%0,%1,%2,%3};"
        : "+f"(c[0]), "+f"(c[1]), "+f"(c[2]), "+f"(c[3])
        : "r"(a[0]), "r"(a[1]), "r"(a[2]), "r"(a[3]), "r"(b0), "r"(b1));
}

#define LDSM_X4(r0, r1, r2, r3, addr) \
    asm volatile("ldmatrix.sync.aligned.m8n8.x4.shared.b16 {%0,%1,%2,%3}, [%4];" \
                 : "=r"(r0), "=r"(r1), "=r"(r2), "=r"(r3) : "r"(addr))
#define LDSM_X4_T(r0, r1, r2, r3, addr) \
    asm volatile("ldmatrix.sync.aligned.m8n8.x4.trans.shared.b16 {%0,%1,%2,%3}, [%4];" \
                 : "=r"(r0), "=r"(r1), "=r"(r2), "=r"(r3) : "r"(addr))

// ---------------- fp32 -> fp16 convert ---------------------------------------
__global__ void to_half(const float* __restrict__ src, __half* __restrict__ dst, int n8)
{
    int i = blockIdx.x * blockDim.x + threadIdx.x;
    if (i >= n8) return;
    float4 a = ((const float4*)src)[i * 2];
    float4 b = ((const float4*)src)[i * 2 + 1];
    __half2 h0 = __floats2half2_rn(a.x, a.y);
    __half2 h1 = __floats2half2_rn(a.z, a.w);
    __half2 h2 = __floats2half2_rn(b.x, b.y);
    __half2 h3 = __floats2half2_rn(b.z, b.w);
    uint4 u;
    u.x = *(const uint32_t*)&h0; u.y = *(const uint32_t*)&h1;
    u.z = *(const uint32_t*)&h2; u.w = *(const uint32_t*)&h3;
    ((uint4*)dst)[i] = u;
}

// ---------------- cos/sin table ----------------------------------------------
__global__ void build_cs(void)
{
    int idx = blockIdx.x * blockDim.x + threadIdx.x;
    if (idx >= T * 32) return;
    int i = idx & 31;
    int t = idx >> 5;
    float inv = 1.0f / powf(10000.0f, (float)(2 * i) / 64.0f);
    float ang = (float)t * inv;
    g_cs[idx] = make_float2(cosf(ang), sinf(ang));
}

// ========= fp16 mma GEMM: C[M,N] = A[M,K] @ W[N,K]^T + bias ==================
// CTA 128x256, 8 warps (warp 64x64), BK=64 halves, 3-stage cp.async.
// Scalar-LDS fragment loads (round-11 proven fastest; do not ldmatrix-ify).
// MODE 0: bias + store fp32 C. MODE 1: qkv epilogue (bias + RoPE -> g_qh/kh/vh).
#define BKC 64
#define HSTR 72                         // halves per row
#define WSTR 36                         // 32-bit words per row
#define STG_A_H (128 * HSTR)
#define STG_H ((128 + 256) * HSTR)      // halves per stage
#define NSTG 3
#define TSM_BYTES (NSTG * STG_H * 2)    // 165888

template <int MODE>
__global__ __launch_bounds__(256, 1) void mma_gemm(
    const __half* __restrict__ A, const __half* __restrict__ W,
    const float* __restrict__ bias, float* __restrict__ C,
    int Nt, int K)
{
    extern __shared__ __half smh[];
    const int tid = threadIdx.x;
    const int wid = tid >> 5;
    const int lane = tid & 31;
    const int g = lane >> 2;
    const int t = lane & 3;
    const int bm = blockIdx.y * 128;
    const int bn = blockIdx.x * 256;
    const int warpM = wid & 1;
    const int warpN = wid >> 1;

    const int lrow = tid >> 1;
    const int lh = tid & 1;
    const uint32_t sb = smem_u32(smh);
    const __half* gA = A + (size_t)(bm + lrow) * K + lh * 32;
    const __half* gW0 = W + (size_t)(bn + lrow) * K + lh * 32;
    const __half* gW1 = W + (size_t)(bn + 128 + lrow) * K + lh * 32;
    const uint32_t soff = (lrow * HSTR + lh * 32) * 2;

    float acc[4][8][4];
#pragma unroll
    for (int mi = 0; mi < 4; mi++)
#pragma unroll
        for (int ni = 0; ni < 8; ni++)
#pragma unroll
            for (int e = 0; e < 4; e++) acc[mi][ni][e] = 0.f;

    const int NC = K / BKC;   // 16

#define ISSUE_CHUNK(c)                                                          \
    do {                                                                        \
        const uint32_t base = sb + ((c) % NSTG) * (STG_H * 2);                  \
        const int k0 = (c) * BKC;                                               \
        _Pragma("unroll")                                                       \
        for (int q = 0; q < 4; q++) {                                           \
            CP_ASYNC16(base + soff + q * 16, gA + k0 + q * 8);                  \
            CP_ASYNC16(base + STG_A_H * 2 + soff + q * 16, gW0 + k0 + q * 8);   \
            CP_ASYNC16(base + (STG_A_H + 128 * HSTR) * 2 + soff + q * 16, gW1 + k0 + q * 8); \
        }                                                                       \
        CP_COMMIT();                                                            \
    } while (0)

    ISSUE_CHUNK(0);
    ISSUE_CHUNK(1);

    for (int c = 0; c < NC; c++) {
        if (c + 1 < NC) CP_WAIT1(); else CP_WAIT0();
        __syncthreads();
        if (c + 2 < NC) ISSUE_CHUNK(c + 2);

        const uint32_t* Ab = (const uint32_t*)(smh + (c % NSTG) * STG_H) + (warpM * 64) * WSTR;
        const uint32_t* Wb = (const uint32_t*)(smh + (c % NSTG) * STG_H) + STG_A_H / 2 + (warpN * 64) * WSTR;

        uint32_t af[2][4][4], bf[2][8][2];
#define LOAD_FRAGS(buf, kw)                                                     \
    do {                                                                        \
        _Pragma("unroll")                                                       \
        for (int mi = 0; mi < 4; mi++) {                                        \
            af[buf][mi][0] = Ab[(mi * 16 + g) * WSTR + (kw) + t];               \
            af[buf][mi][1] = Ab[(mi * 16 + 8 + g) * WSTR + (kw) + t];           \
            af[buf][mi][2] = Ab[(mi * 16 + g) * WSTR + (kw) + t + 4];           \
            af[buf][mi][3] = Ab[(mi * 16 + 8 + g) * WSTR + (kw) + t + 4];       \
        }                                                                       \
        _Pragma("unroll")                                                       \
        for (int ni = 0; ni < 8; ni++) {                                        \
            bf[buf][ni][0] = Wb[(ni * 8 + g) * WSTR + (kw) + t];                \
            bf[buf][ni][1] = Wb[(ni * 8 + g) * WSTR + (kw) + t + 4];            \
        }                                                                       \
    } while (0)

        LOAD_FRAGS(0, 0);
#pragma unroll
        for (int ks = 0; ks < 4; ks++) {
            const int cur = ks & 1;
            if (ks < 3) LOAD_FRAGS(cur ^ 1, (ks + 1) * 8);
#pragma unroll
            for (int mi = 0; mi < 4; mi++)
#pragma unroll
                for (int ni = 0; ni < 8; ni++)
                    mma_f16(acc[mi][ni], af[cur][mi], bf[cur][ni][0], bf[cur][ni][1]);
        }
#undef LOAD_FRAGS
    }

    if (MODE == 0) {
#pragma unroll
        for (int mi = 0; mi < 4; mi++) {
            const int row0 = bm + warpM * 64 + mi * 16 + g;
#pragma unroll
            for (int ni = 0; ni < 8; ni++) {
                const int col = bn + warpN * 64 + ni * 8 + 2 * t;
                const float bx = bias[col], by = bias[col + 1];
                float2 r0, r1;
                r0.x = acc[mi][ni][0] + bx; r0.y = acc[mi][ni][1] + by;
                r1.x = acc[mi][ni][2] + bx; r1.y = acc[mi][ni][3] + by;
                *(float2*)(C + (size_t)row0 * Nt + col) = r0;
                *(float2*)(C + (size_t)(row0 + 8) * Nt + col) = r1;
            }
        }
    } else {
        // qkv epilogue: warp slab = one head of q/k/v. bias + RoPE + fp16 scatter.
        const int col0 = bn + warpN * 64;
        const int region = col0 >> 10;               // 0=q 1=k 2=v
        const int h = (col0 & 1023) >> 6;
        __half* dst = (region == 0) ? g_qh : (region == 1) ? g_kh : g_vh;
#pragma unroll
        for (int mi = 0; mi < 4; mi++) {
            const int rowg = bm + warpM * 64 + mi * 16 + g;
#pragma unroll
            for (int rs = 0; rs < 2; rs++) {
                const int row = rowg + rs * 8;
                const int tt = row & (T - 1);
                const int bb = row >> 11;
                __half* op = dst + ((size_t)(bb * HEADS + h) * T + tt) * HDIM;
                const float2* cs = g_cs + tt * 32;
#pragma unroll
                for (int ni = 0; ni < 4; ni++) {
#pragma unroll
                    for (int e = 0; e < 2; e++) {
                        const int d = ni * 8 + 2 * t + e;
                        float v1 = acc[mi][ni][rs * 2 + e] + bias[col0 + d];
                        float v2 = acc[mi][ni + 4][rs * 2 + e] + bias[col0 + d + 32];
                        if (region < 2) {
                            float2 c = cs[d];
                            op[d]      = __float2half_rn(v1 * c.x - v2 * c.y);
                            op[d + 32] = __float2half_rn(v1 * c.y + v2 * c.x);
                        } else {
                            op[d]      = __float2half_rn(v1);
                            op[d + 32] = __float2half_rn(v2);
                        }
                    }
                }
            }
        }
    }
#undef ISSUE_CHUNK
}

// ================== fp16 tensor-core flash attention =========================
// CTA: 128 q rows x (head,batch); 4 warps. KV tile = 64 keys, double-buffered
// cp.async, P register-resident. Heavy q-tiles scheduled FIRST (LPT).
#define HSTRF 72
#define FK_H (64 * HSTRF)
#define FSTG_H (2 * FK_H)
#define FSM_BYTES (2 * FSTG_H * 2)

__global__ __launch_bounds__(128) void flash_mma(
    const int* __restrict__ ids, const long long* __restrict__ gidx, int n_g)
{
    extern __shared__ __half fsm[];
    __shared__ int s_anyg;

    const int tid = threadIdx.x;
    const int w = tid >> 5;
    const int lane = tid & 31;
    const int g = lane >> 2;
    const int t = lane & 3;
    const int qb = gridDim.x - 1 - blockIdx.x;   // heavy (large-qb) blocks first
    const int h = blockIdx.y;
    const int b = blockIdx.z;
    const int bh = b * HEADS + h;
    const int qrow0 = qb * 128;

    if (tid == 0) s_anyg = 0;
    __syncthreads();
    {
        int myid = ids[b * T + qrow0 + tid];
        bool myg = false;
        for (int i = 0; i < n_g; i++) myg |= (myid == (int)gidx[i]);
        if (myg) s_anyg = 1;
    }
    unsigned gmask;
    {
        int rid = ids[b * T + qrow0 + w * 32 + lane];
        bool rg = false;
        for (int i = 0; i < n_g; i++) rg |= (rid == (int)gidx[i]);
        gmask = __ballot_sync(0xffffffffu, rg);
    }
    __syncthreads();
    const int ktmax = s_anyg ? (T / 64 - 1) : (2 * qb + 1);

    uint32_t q[2][4][4];
    {
        const __half* Qb = g_qh + ((size_t)bh * T + qrow0 + w * 32) * HDIM;
        const __half2 qsc = __floats2half2_rn(0.125f, 0.125f);
#pragma unroll
        for (int rb = 0; rb < 2; rb++)
#pragma unroll
            for (int ks = 0; ks < 4; ks++) {
                const __half* b0 = Qb + (rb * 16 + g) * HDIM + ks * 16 + 2 * t;
                const __half* b1 = Qb + (rb * 16 + 8 + g) * HDIM + ks * 16 + 2 * t;
                __half2 a0 = __hmul2(*(const __half2*)b0, qsc);
                __half2 a1 = __hmul2(*(const __half2*)b1, qsc);
                __half2 a2 = __hmul2(*(const __half2*)(b0 + 8), qsc);
                __half2 a3 = __hmul2(*(const __half2*)(b1 + 8), qsc);
                q[rb][ks][0] = *(uint32_t*)&a0;
                q[rb][ks][1] = *(uint32_t*)&a1;
                q[rb][ks][2] = *(uint32_t*)&a2;
                q[rb][ks][3] = *(uint32_t*)&a3;
            }
    }

    float o[2][8][4];
#pragma unroll
    for (int rb = 0; rb < 2; rb++)
#pragma unroll
        for (int f = 0; f < 8; f++)
#pragma unroll
            for (int e = 0; e < 4; e++) o[rb][f][e] = 0.f;
    float m_[2][2], l_[2][2];
#pragma unroll
    for (int rb = 0; rb < 2; rb++)
#pragma unroll
        for (int hh = 0; hh < 2; hh++) { m_[rb][hh] = -1e30f; l_[rb][hh] = 0.f; }

    const __half* Kgb = g_kh + (size_t)bh * T * HDIM;
    const __half* Vgb = g_vh + (size_t)bh * T * HDIM;
    const uint32_t fsb = smem_u32(fsm);

    const int keyLK = ((lane >> 4) & 1) * 8 + (lane & 7);
    const int dLK = ((lane >> 3) & 1) * 8;
    const int keyLV = ((lane >> 3) & 1) * 8 + (lane & 7);
    const int dLV = (lane >> 4) * 8;
    const uint32_t kLaneOff = (uint32_t)(keyLK * HSTRF + dLK) * 2;
    const uint32_t vLaneOff = (uint32_t)(keyLV * HSTRF + dLV) * 2;

#define FISSUE(kt)                                                              \
    do {                                                                        \
        const uint32_t base = fsb + ((kt) & 1) * (FSTG_H * 2);                  \
        const __half* Ksrc = Kgb + (size_t)(kt) * 64 * HDIM;                    \
        const __half* Vsrc = Vgb + (size_t)(kt) * 64 * HDIM;                    \
        _Pragma("unroll")                                                       \
        for (int j = 0; j < 4; j++) {                                           \
            int idx = tid + j * 128;                                            \
            int r = idx >> 3;                                                   \
            int s8 = idx & 7;                                                   \
            CP_ASYNC16(base + (r * HSTRF + s8 * 8) * 2, Ksrc + r * HDIM + s8 * 8); \
            CP_ASYNC16(base + (FK_H + r * HSTRF + s8 * 8) * 2, Vsrc + r * HDIM + s8 * 8); \
        }                                                                       \
        CP_COMMIT();                                                            \
    } while (0)

    FISSUE(0);

    for (int kt = 0; kt <= ktmax; kt++) {
        __syncthreads();
        if (kt + 1 <= ktmax) { FISSUE(kt + 1); CP_WAIT1(); } else { CP_WAIT0(); }
        __syncthreads();
        const uint32_t ksm = fsb + (kt & 1) * (FSTG_H * 2);
        const uint32_t vsm = ksm + FK_H * 2;

        float s[2][8][4];
#pragma unroll
        for (int rb = 0; rb < 2; rb++)
#pragma unroll
            for (int f = 0; f < 8; f++)
#pragma unroll
                for (int e = 0; e < 4; e++) s[rb][f][e] = 0.f;
#pragma unroll
        for (int ks = 0; ks < 4; ks++) {
#pragma unroll
            for (int fp = 0; fp < 4; fp++) {
                uint32_t b0, b1, b2, b3;
                uint32_t addr = ksm + kLaneOff + (uint32_t)(fp * 16 * HSTRF + ks * 16) * 2;
                LDSM_X4(b0, b1, b2, b3, addr);
                mma_f16(s[0][fp * 2], q[0][ks], b0, b1);
                mma_f16(s[1][fp * 2], q[1][ks], b0, b1);
                mma_f16(s[0][fp * 2 + 1], q[0][ks], b2, b3);
                mma_f16(s[1][fp * 2 + 1], q[1][ks], b2, b3);
            }
        }

        uint32_t ap[2][4][4];
#pragma unroll
        for (int rb = 0; rb < 2; rb++) {
#pragma unroll
            for (int hh = 0; hh < 2; hh++) {
                const int rloc = rb * 16 + hh * 8 + g;
                const int grow = qrow0 + w * 32 + rloc;
                const bool rowg = (gmask >> rloc) & 1u;
                float pv[16];
                float mx = -1e30f;
                const bool fullok = (kt * 64 + 63 <= grow) || rowg;
#pragma unroll
                for (int f = 0; f < 8; f++) {
#pragma unroll
                    for (int e = 0; e < 2; e++) {
                        float sv = s[rb][f][hh * 2 + e];
                        if (!fullok) {
                            int col = kt * 64 + f * 8 + 2 * t + e;
                            if (col > grow) sv = -1e30f;
                        }
                        pv[f * 2 + e] = sv;
                        mx = fmaxf(mx, sv);
                    }
                }
                mx = fmaxf(mx, __shfl_xor_sync(0xffffffffu, mx, 1));
                mx = fmaxf(mx, __shfl_xor_sync(0xffffffffu, mx, 2));
                float mold = m_[rb][hh];
                float mnew = fmaxf(mold, mx);
                float corr = __expf(mold - mnew);
                float lsum = 0.f;
#pragma unroll
                for (int i = 0; i < 16; i++) {
                    float p = __expf(pv[i] - mnew);
                    pv[i] = p;
                    lsum += p;
                }
                lsum += __shfl_xor_sync(0xffffffffu, lsum, 1);
                lsum += __shfl_xor_sync(0xffffffffu, lsum, 2);
                m_[rb][hh] = mnew;
                l_[rb][hh] = l_[rb][hh] * corr + lsum;
#pragma unroll
                for (int f = 0; f < 8; f++) {
                    o[rb][f][hh * 2] *= corr;
                    o[rb][f][hh * 2 + 1] *= corr;
                }
#pragma unroll
                for (int ks = 0; ks < 4; ks++) {
                    __half2 lo = __floats2half2_rn(pv[4 * ks], pv[4 * ks + 1]);
                    __half2 hi = __floats2half2_rn(pv[4 * ks + 2], pv[4 * ks + 3]);
                    ap[rb][ks][hh] = *(uint32_t*)&lo;
                    ap[rb][ks][2 + hh] = *(uint32_t*)&hi;
                }
            }
        }

#pragma unroll
        for (int ks = 0; ks < 4; ks++) {
#pragma unroll
            for (int fp = 0; fp < 4; fp++) {
                uint32_t b0, b1, b2, b3;
                uint32_t addr = vsm + vLaneOff + (uint32_t)(ks * 16 * HSTRF + fp * 16) * 2;
                LDSM_X4_T(b0, b1, b2, b3, addr);
                mma_f16(o[0][fp * 2], ap[0][ks], b0, b1);
                mma_f16(o[1][fp * 2], ap[1][ks], b0, b1);
                mma_f16(o[0][fp * 2 + 1], ap[0][ks], b2, b3);
                mma_f16(o[1][fp * 2 + 1], ap[1][ks], b2, b3);
            }
        }
    }
#undef FISSUE

#pragma unroll
    for (int rb = 0; rb < 2; rb++) {
#pragma unroll
        for (int hh = 0; hh < 2; hh++) {
            float invl = 1.0f / l_[rb][hh];
            int trow = qrow0 + w * 32 + rb * 16 + hh * 8 + g;
            __half* op = g_ctx + ((size_t)b * T + trow) * HIDDEN + h * 64;
#pragma unroll
            for (int f = 0; f < 8; f++) {
                __half2 hr = __floats2half2_rn(o[rb][f][hh * 2] * invl,
                                               o[rb][f][hh * 2 + 1] * invl);
                *(__half2*)(op + f * 8 + 2 * t) = hr;
            }
        }
    }
}

// ---------------- host launch ------------------------------------------------
extern "C" void kernel_launch(void* const* d_in, const int* in_sizes, int n_in,
                              void* d_out, int out_size)
{
    const float* x      = (const float*)d_in[0];
    const int*   ids    = (const int*)d_in[1];
    const float* qkv_w  = (const float*)d_in[2];
    const float* qkv_b  = (const float*)d_in[3];
    const float* out_w  = (const float*)d_in[4];
    const float* out_b  = (const float*)d_in[5];
    const long long* gi = (const long long*)d_in[6];
    const int n_g = in_sizes[6];
    float* out = (float*)d_out;

    __half *p_xh, *p_wqkvh, *p_wouth, *p_ctx;
    cudaGetSymbolAddress((void**)&p_xh, g_xh);
    cudaGetSymbolAddress((void**)&p_wqkvh, g_wqkvh);
    cudaGetSymbolAddress((void**)&p_wouth, g_wouth);
    cudaGetSymbolAddress((void**)&p_ctx, g_ctx);

    cudaFuncSetAttribute(mma_gemm<0>,
                         cudaFuncAttributeMaxDynamicSharedMemorySize, TSM_BYTES);
    cudaFuncSetAttribute(mma_gemm<1>,
                         cudaFuncAttributeMaxDynamicSharedMemorySize, TSM_BYTES);
    cudaFuncSetAttribute(flash_mma,
                         cudaFuncAttributeMaxDynamicSharedMemorySize, FSM_BYTES);

    // 0) converts + cos/sin table
    to_half<<<(BT * HIDDEN / 8 + 255) / 256, 256>>>(x, p_xh, BT * HIDDEN / 8);
    to_half<<<(QKV3 * HIDDEN / 8 + 255) / 256, 256>>>(qkv_w, p_wqkvh, QKV3 * HIDDEN / 8);
    to_half<<<(HIDDEN * HIDDEN / 8 + 255) / 256, 256>>>(out_w, p_wouth, HIDDEN * HIDDEN / 8);
    build_cs<<<(T * 32 + 255) / 256, 256>>>();

    // 1) QKV projection + bias + RoPE + fp16 scatter to g_qh/g_kh/g_vh
    {
        dim3 grid(QKV3 / 256, BT / 128);
        mma_gemm<1><<<grid, 256, TSM_BYTES>>>(p_xh, p_wqkvh, qkv_b, nullptr, QKV3, HIDDEN);
    }
    // 2) Flash attention (fp16 tensor cores, register-resident P, LPT order)
    {
        dim3 grid(T / 128, HEADS, B);
        flash_mma<<<grid, 128, FSM_BYTES>>>(ids, gi, n_g);
    }
    // 3) Output projection (fp16 operands, fp32 accum/output)
    {
        dim3 grid(HIDDEN / 256, BT / 128);
        mma_gemm<0><<<grid, 256, TSM_BYTES>>>(p_ctx, p_wouth, out_b, out, HIDDEN, HIDDEN);
    }
}